// round 14
// baseline (speedup 1.0000x reference)
#include <cuda_runtime.h>
#include <cuda_fp16.h>
#include <stdint.h>

#define T_TOK 2048
#define KDIM  2048
#define IDIM  1024
#define NEXP  8
#define NJOBS 9
#define CAP   4096
#define TOPK  2

#define A_STRIDE 72
#define B_STRIDE 136
#define ABUF (128 * A_STRIDE * 2)          // 18432 B per stage
#define BBUF (64 * B_STRIDE * 2)           // 17408 B per stage
#define BOFF (2 * ABUF)                    // 36864
#define TSOFF (BOFF + 2 * BBUF)            // 71680
#define DSMEM (TSOFF + 512)                // 72192  (3 CTAs/SM: 216.6KB)

// ---------------- scratch (device globals) ----------------
__device__ int   g_cnt[NJOBS];
__device__ int   g_tok[NJOBS * CAP];
__device__ int   g_slot[T_TOK * TOPK];
__device__ __align__(16) __half g_xh[(size_t)T_TOK * KDIM];                 // [t][k]
__device__ __align__(16) __half g_wgu[(size_t)NJOBS * KDIM * 2 * IDIM];     // [job][k][2I]
__device__ __align__(16) __half g_wd [(size_t)NJOBS * IDIM * KDIM];         // [job][i][K]
__device__ __align__(16) __half g_acth[(size_t)NJOBS * CAP * IDIM];         // [job][slot][i]
__device__ __align__(16) __half g_y[(size_t)NJOBS * CAP * KDIM];            // [slot][k] fp16

// ---------------- helpers ----------------
__device__ __forceinline__ uint32_t sptr(const void* p) {
    return (uint32_t)__cvta_generic_to_shared(p);
}
__device__ __forceinline__ void cp16(uint32_t dst, const void* src) {
    asm volatile("cp.async.cg.shared.global [%0], [%1], 16;" :: "r"(dst), "l"(src));
}
__device__ __forceinline__ void cpcommit() { asm volatile("cp.async.commit_group;"); }
__device__ __forceinline__ void cpwait0()  { asm volatile("cp.async.wait_group 0;"); }

__device__ __forceinline__ void ldsm4(uint32_t* r, uint32_t a) {
    asm volatile("ldmatrix.sync.aligned.m8n8.x4.shared.b16 {%0,%1,%2,%3}, [%4];"
        : "=r"(r[0]), "=r"(r[1]), "=r"(r[2]), "=r"(r[3]) : "r"(a));
}
__device__ __forceinline__ void ldsm4t(uint32_t* r, uint32_t a) {
    asm volatile("ldmatrix.sync.aligned.m8n8.x4.trans.shared.b16 {%0,%1,%2,%3}, [%4];"
        : "=r"(r[0]), "=r"(r[1]), "=r"(r[2]), "=r"(r[3]) : "r"(a));
}
__device__ __forceinline__ void mma16816(float* d, const uint32_t* a, uint32_t b0, uint32_t b1) {
    asm volatile("mma.sync.aligned.m16n8k16.row.col.f32.f16.f16.f32 "
        "{%0,%1,%2,%3},{%4,%5,%6,%7},{%8,%9},{%0,%1,%2,%3};"
        : "+f"(d[0]), "+f"(d[1]), "+f"(d[2]), "+f"(d[3])
        : "r"(a[0]), "r"(a[1]), "r"(a[2]), "r"(a[3]), "r"(b0), "r"(b1));
}

// ---------------- small kernels ----------------
__global__ void k_route(const int* __restrict__ ids) {
    int t = blockIdx.x * 256 + threadIdx.x;
    for (int s = 0; s < TOPK; s++) {
        int e   = ids[t * TOPK + s];
        int pos = atomicAdd(&g_cnt[e], 1);
        int slot = e * CAP + pos;
        g_tok[slot] = t;
        g_slot[t * TOPK + s] = slot;
    }
    g_tok[NEXP * CAP + t] = t;
    if (t == 0) g_cnt[NEXP] = T_TOK;
}

__global__ void k_x2h(const float* __restrict__ x) {
    int i = blockIdx.x * 256 + threadIdx.x;
    g_xh[i] = __float2half_rn(x[i]);
}

// ---------------- kernel: dequant (register transpose, no smem) ----------------
__global__ __launch_bounds__(256) void k_dq(
    const int* __restrict__ Wq, const float* __restrict__ S,
    const int* __restrict__ Wqs, const float* __restrict__ Ss,
    __half* __restrict__ Out, int Kd, int Nd)
{
    const int job = blockIdx.y;
    const int* W; const float* Sc;
    if (job < NEXP) {
        W  = Wq + (size_t)job * (Kd >> 3) * Nd;
        Sc = S  + (size_t)job * (Kd >> 6) * Nd;
    } else { W = Wqs; Sc = Ss; }
    __half* O = Out + (size_t)job * Kd * Nd;

    const int g  = blockIdx.x * 256 + threadIdx.x;
    const int oN = Nd >> 3;
    const int kw = g / oN;
    const int n  = (g - kw * oN) * 8;

    const int4 wv0 = *(const int4*)(W + (size_t)kw * Nd + n);
    const int4 wv1 = *(const int4*)(W + (size_t)kw * Nd + n + 4);
    const float4 sv0 = *(const float4*)(Sc + (size_t)(kw >> 3) * Nd + n);
    const float4 sv1 = *(const float4*)(Sc + (size_t)(kw >> 3) * Nd + n + 4);
    const float s0 = sv0.x * 16384.0f, s1 = sv0.y * 16384.0f;
    const float s2 = sv0.z * 16384.0f, s3 = sv0.w * 16384.0f;
    const float s4 = sv1.x * 16384.0f, s5 = sv1.y * 16384.0f;
    const float s6 = sv1.z * 16384.0f, s7 = sv1.w * 16384.0f;
    const uint32_t w0 = (uint32_t)wv0.x, w1 = (uint32_t)wv0.y;
    const uint32_t w2 = (uint32_t)wv0.z, w3 = (uint32_t)wv0.w;
    const uint32_t w4 = (uint32_t)wv1.x, w5 = (uint32_t)wv1.y;
    const uint32_t w6 = (uint32_t)wv1.z, w7 = (uint32_t)wv1.w;

    __half* orow = O + (size_t)(kw * 8) * Nd + n;
    #pragma unroll
    for (int k = 0; k < 8; k++) {
        uint32_t u0 = ((w0 >> (4 * k)) & 0xFu) | (((w1 >> (4 * k)) & 0xFu) << 16);
        uint32_t u1 = ((w2 >> (4 * k)) & 0xFu) | (((w3 >> (4 * k)) & 0xFu) << 16);
        uint32_t u2 = ((w4 >> (4 * k)) & 0xFu) | (((w5 >> (4 * k)) & 0xFu) << 16);
        uint32_t u3 = ((w6 >> (4 * k)) & 0xFu) | (((w7 >> (4 * k)) & 0xFu) << 16);
        uint32_t h0 = ((u0 & 0x00070007u) << 9) | ((u0 & 0x00080008u) << 12);
        uint32_t h1 = ((u1 & 0x00070007u) << 9) | ((u1 & 0x00080008u) << 12);
        uint32_t h2 = ((u2 & 0x00070007u) << 9) | ((u2 & 0x00080008u) << 12);
        uint32_t h3 = ((u3 & 0x00070007u) << 9) | ((u3 & 0x00080008u) << 12);
        float2 f0 = __half22float2(*reinterpret_cast<__half2*>(&h0));
        float2 f1 = __half22float2(*reinterpret_cast<__half2*>(&h1));
        float2 f2 = __half22float2(*reinterpret_cast<__half2*>(&h2));
        float2 f3 = __half22float2(*reinterpret_cast<__half2*>(&h3));
        __half2 r0 = __floats2half2_rn(f0.x * s0, f0.y * s1);
        __half2 r1 = __floats2half2_rn(f1.x * s2, f1.y * s3);
        __half2 r2 = __floats2half2_rn(f2.x * s4, f2.y * s5);
        __half2 r3 = __floats2half2_rn(f3.x * s6, f3.y * s7);
        uint4 st;
        st.x = *reinterpret_cast<uint32_t*>(&r0);
        st.y = *reinterpret_cast<uint32_t*>(&r1);
        st.z = *reinterpret_cast<uint32_t*>(&r2);
        st.w = *reinterpret_cast<uint32_t*>(&r3);
        *(uint4*)(orow + (size_t)k * Nd) = st;
    }
}

// ---------------- kernel: gate_up HMMA GEMM + silu ----------------
// 256 threads = 8 warps (4m x 2n). M=128, tile cols 128 (64 gate | 64 up),
// BK=64, 2-stage cp.async, 3 CTAs/SM.
__global__ __launch_bounds__(256, 3) void k_gemm1() {
    extern __shared__ __align__(16) char sm[];
    int* ts = (int*)(sm + TSOFF);

    const int job  = blockIdx.z;
    const int cnt  = g_cnt[job];
    const int base = blockIdx.x * 128;
    if (base >= cnt) return;

    const int n0   = blockIdx.y * 64;
    const int tid  = threadIdx.x;
    const int lane = tid & 31;
    const int warp = tid >> 5;
    const int wm   = (warp >> 1) * 32;
    const int wn   = (warp & 1) * 64;
    const int pair = warp & 1;
    const __half* Wj = g_wgu + (size_t)job * KDIM * (2 * IDIM);

    if (tid < 128) {
        int p = base + tid;
        ts[tid] = (p < cnt) ? g_tok[job * CAP + p] : 0;
    }
    __syncthreads();

    int arow[4], aseg[4], atok[4], aoff[4];
    for (int i = 0; i < 4; i++) {
        int c   = tid + i * 256;
        arow[i] = c >> 3;
        aseg[i] = c & 7;
        atok[i] = ts[arow[i]];
        aoff[i] = (arow[i] * A_STRIDE + aseg[i] * 8) * 2;
    }
    int bkr[4], boff[4], bgc[4];
    for (int i = 0; i < 4; i++) {
        int c   = tid + i * 256;
        bkr[i]  = c >> 4;
        int seg = c & 15;
        boff[i] = (bkr[i] * B_STRIDE + seg * 8) * 2;
        int p2  = seg >> 3;
        int sub = (seg & 7) * 8;
        bgc[i]  = (sub < 32) ? (n0 + p2 * 32 + sub)
                             : (IDIM + n0 + p2 * 32 + (sub - 32));
    }

    const uint32_t asb = sptr(sm);
    const uint32_t bsb = asb + BOFF;
    const uint32_t a_frag = asb + ((wm + (lane & 15)) * A_STRIDE + (lane >> 4) * 8) * 2;
    const uint32_t b_frag = bsb + ((lane & 15) * B_STRIDE + wn + (lane >> 4) * 8) * 2;

    float acc[2][8][4];
    for (int i = 0; i < 2; i++)
        for (int j = 0; j < 8; j++)
            for (int k = 0; k < 4; k++) acc[i][j][k] = 0.f;

    auto fill = [&](int c, int buf) {
        int kc = c * 64;
        for (int i = 0; i < 4; i++)
            cp16(asb + buf * ABUF + aoff[i],
                 g_xh + (size_t)atok[i] * KDIM + kc + aseg[i] * 8);
        for (int i = 0; i < 4; i++)
            cp16(bsb + buf * BBUF + boff[i],
                 Wj + (size_t)(kc + bkr[i]) * (2 * IDIM) + bgc[i]);
        cpcommit();
    };

    fill(0, 0);

    const int C = KDIM / 64;
    for (int c = 0; c < C; c++) {
        cpwait0();
        __syncthreads();
        if (c + 1 < C) fill(c + 1, (c + 1) & 1);   // buf last read in iter c-1
        int buf = c & 1;
        uint32_t ab = a_frag + buf * ABUF;
        uint32_t bb = b_frag + buf * BBUF;
        for (int ks = 0; ks < 4; ks++) {
            uint32_t a0[4], a1[4];
            ldsm4(a0, ab + ks * 32);
            ldsm4(a1, ab + ks * 32 + 16 * A_STRIDE * 2);
            for (int jp = 0; jp < 4; jp++) {
                uint32_t b[4];
                ldsm4t(b, bb + jp * 32 + ks * (16 * B_STRIDE * 2));
                mma16816(acc[0][jp * 2 + 0], a0, b[0], b[1]);
                mma16816(acc[1][jp * 2 + 0], a1, b[0], b[1]);
                mma16816(acc[0][jp * 2 + 1], a0, b[2], b[3]);
                mma16816(acc[1][jp * 2 + 1], a1, b[2], b[3]);
            }
        }
    }

    __half* actb = g_acth + (size_t)job * CAP * IDIM;
    for (int am = 0; am < 2; am++) {
        for (int h = 0; h < 2; h++) {
            int r   = wm + am * 16 + (lane >> 2) + h * 8;
            int pos = base + r;
            if (pos >= cnt) continue;
            __half* orow = actb + (size_t)pos * IDIM;
            for (int jp = 0; jp < 2; jp++) {
                for (int jj = 0; jj < 2; jj++) {
                    float g0 = acc[am][jp * 2 + jj][h * 2 + 0];
                    float g1 = acc[am][jp * 2 + jj][h * 2 + 1];
                    float u0 = acc[am][(jp + 2) * 2 + jj][h * 2 + 0];
                    float u1 = acc[am][(jp + 2) * 2 + jj][h * 2 + 1];
                    float o0 = g0 / (1.0f + __expf(-g0)) * u0;
                    float o1 = g1 / (1.0f + __expf(-g1)) * u1;
                    int col = n0 + pair * 32 + jp * 16 + jj * 8 + (lane & 3) * 2;
                    *(__half2*)(orow + col) = __floats2half2_rn(o0, o1);
                }
            }
        }
    }
}

// ---------------- kernel: down HMMA GEMM -> g_y (fp16) ----------------
// Tile M=128 slots x N=128 K-cols, BK=64, 2-stage cp.async, 3 CTAs/SM.
__global__ __launch_bounds__(256, 3) void k_gemm2() {
    extern __shared__ __align__(16) char sm[];

    const int job  = blockIdx.z;
    const int cnt  = g_cnt[job];
    const int base = blockIdx.x * 128;
    if (base >= cnt) return;

    const int n0   = blockIdx.y * 128;
    const int tid  = threadIdx.x;
    const int lane = tid & 31;
    const int warp = tid >> 5;
    const int wm   = (warp >> 1) * 32;
    const int wn   = (warp & 1) * 64;
    const __half* Wj = g_wd + (size_t)job * IDIM * KDIM;
    const __half* Ab = g_acth + (size_t)job * CAP * IDIM;

    int arow[4], aseg[4], aoff[4];
    for (int i = 0; i < 4; i++) {
        int c   = tid + i * 256;
        arow[i] = c >> 3;
        aseg[i] = c & 7;
        aoff[i] = (arow[i] * A_STRIDE + aseg[i] * 8) * 2;
    }
    int bkr[4], boff[4], bgc[4];
    for (int i = 0; i < 4; i++) {
        int c   = tid + i * 256;
        bkr[i]  = c >> 4;
        int seg = c & 15;
        boff[i] = (bkr[i] * B_STRIDE + seg * 8) * 2;
        bgc[i]  = n0 + seg * 8;
    }

    const uint32_t asb = sptr(sm);
    const uint32_t bsb = asb + BOFF;
    const uint32_t a_frag = asb + ((wm + (lane & 15)) * A_STRIDE + (lane >> 4) * 8) * 2;
    const uint32_t b_frag = bsb + ((lane & 15) * B_STRIDE + wn + (lane >> 4) * 8) * 2;

    float acc[2][8][4];
    for (int i = 0; i < 2; i++)
        for (int j = 0; j < 8; j++)
            for (int k = 0; k < 4; k++) acc[i][j][k] = 0.f;

    auto fill = [&](int c, int buf) {
        int kc = c * 64;
        for (int i = 0; i < 4; i++)
            cp16(asb + buf * ABUF + aoff[i],
                 Ab + (size_t)(base + arow[i]) * IDIM + kc + aseg[i] * 8);
        for (int i = 0; i < 4; i++)
            cp16(bsb + buf * BBUF + boff[i],
                 Wj + (size_t)(kc + bkr[i]) * KDIM + bgc[i]);
        cpcommit();
    };

    fill(0, 0);

    const int C = IDIM / 64;
    for (int c = 0; c < C; c++) {
        cpwait0();
        __syncthreads();
        if (c + 1 < C) fill(c + 1, (c + 1) & 1);
        int buf = c & 1;
        uint32_t ab = a_frag + buf * ABUF;
        uint32_t bb = b_frag + buf * BBUF;
        for (int ks = 0; ks < 4; ks++) {
            uint32_t a0[4], a1[4];
            ldsm4(a0, ab + ks * 32);
            ldsm4(a1, ab + ks * 32 + 16 * A_STRIDE * 2);
            for (int jp = 0; jp < 4; jp++) {
                uint32_t b[4];
                ldsm4t(b, bb + jp * 32 + ks * (16 * B_STRIDE * 2));
                mma16816(acc[0][jp * 2 + 0], a0, b[0], b[1]);
                mma16816(acc[1][jp * 2 + 0], a1, b[0], b[1]);
                mma16816(acc[0][jp * 2 + 1], a0, b[2], b[3]);
                mma16816(acc[1][jp * 2 + 1], a1, b[2], b[3]);
            }
        }
    }

    __half* yb = g_y + (size_t)job * CAP * KDIM;
    for (int am = 0; am < 2; am++) {
        for (int h = 0; h < 2; h++) {
            int r   = wm + am * 16 + (lane >> 2) + h * 8;
            int pos = base + r;
            if (pos >= cnt) continue;
            __half* orow = yb + (size_t)pos * KDIM;
            for (int j = 0; j < 8; j++) {
                int col = n0 + wn + (j >> 1) * 16 + (j & 1) * 8 + (lane & 3) * 2;
                *(__half2*)(orow + col) =
                    __floats2half2_rn(acc[am][j][h * 2 + 0], acc[am][j][h * 2 + 1]);
            }
        }
    }
}

// ---------------- kernel: combine routed + shared -> out; reset counters ----
__global__ __launch_bounds__(256) void k_combine(float* __restrict__ out,
                                                 const float* __restrict__ probs) {
    const int t = blockIdx.x;
    const uint4* y0 = (const uint4*)(g_y + (size_t)g_slot[t * TOPK + 0] * KDIM);
    const uint4* y1 = (const uint4*)(g_y + (size_t)g_slot[t * TOPK + 1] * KDIM);
    const uint4* ys = (const uint4*)(g_y + (size_t)(NEXP * CAP + t) * KDIM);
    const float p0 = probs[t * TOPK + 0];
    const float p1 = probs[t * TOPK + 1];
    float4* o = (float4*)(out + (size_t)t * KDIM);
    const int i = threadIdx.x;
    uint4 a = y0[i], b = y1[i], s = ys[i];
    const uint32_t* ap = (const uint32_t*)&a;
    const uint32_t* bp = (const uint32_t*)&b;
    const uint32_t* sp = (const uint32_t*)&s;
    float4 r0, r1;
    for (int j = 0; j < 4; j++) {
        float2 fa = __half22float2(*(const __half2*)&ap[j]);
        float2 fb = __half22float2(*(const __half2*)&bp[j]);
        float2 fs = __half22float2(*(const __half2*)&sp[j]);
        float* dst = (j < 2) ? ((float*)&r0 + j * 2) : ((float*)&r1 + (j - 2) * 2);
        dst[0] = p0 * fa.x + p1 * fb.x + fs.x;
        dst[1] = p0 * fa.y + p1 * fb.y + fs.y;
    }
    o[i * 2]     = r0;
    o[i * 2 + 1] = r1;
    if (blockIdx.x == 0 && threadIdx.x < NJOBS) g_cnt[threadIdx.x] = 0;
}

// ---------------- launcher ----------------
extern "C" void kernel_launch(void* const* d_in, const int* in_sizes, int n_in,
                              void* d_out, int out_size) {
    const float* x     = (const float*)d_in[0];
    const int*   gup   = (const int*)  d_in[1];
    const float* gus   = (const float*)d_in[2];
    const int*   dwp   = (const int*)  d_in[3];
    const float* dws   = (const float*)d_in[4];
    const int*   sgup  = (const int*)  d_in[5];
    const float* sgus  = (const float*)d_in[6];
    const int*   sdp   = (const int*)  d_in[7];
    const float* sds   = (const float*)d_in[8];
    const int*   ids   = (const int*)  d_in[9];
    const float* probs = (const float*)d_in[10];
    float* out = (float*)d_out;

    cudaFuncSetAttribute(k_gemm1, cudaFuncAttributeMaxDynamicSharedMemorySize, DSMEM);
    cudaFuncSetAttribute(k_gemm2, cudaFuncAttributeMaxDynamicSharedMemorySize, DSMEM);

    __half* wgu;
    __half* wd;
    cudaGetSymbolAddress((void**)&wgu, g_wgu);
    cudaGetSymbolAddress((void**)&wd,  g_wd);

    // Launch order keeps k_gemm1 at profile slot #4.
    k_x2h  <<<(T_TOK * KDIM) / 256, 256>>>(x);                                  // 1
    k_route<<<T_TOK / 256, 256>>>(ids);                                         // 2
    k_dq<<<dim3((KDIM / 8) * (2 * IDIM / 8) / 256, NJOBS), 256>>>(              // 3
        gup, gus, sgup, sgus, wgu, KDIM, 2 * IDIM);
    k_gemm1<<<dim3(CAP / 128, IDIM / 64, NJOBS), 256, DSMEM>>>();               // 4
    k_dq<<<dim3((IDIM / 8) * (KDIM / 8) / 256, NJOBS), 256>>>(                  // 5
        dwp, dws, sdp, sds, wd, IDIM, KDIM);
    k_gemm2<<<dim3(CAP / 128, KDIM / 128, NJOBS), 256, DSMEM>>>();              // 6
    k_combine<<<T_TOK, 256>>>(out, probs);                                      // 7
}

// round 15
// speedup vs baseline: 1.4848x; 1.4848x over previous
#include <cuda_runtime.h>
#include <cuda_fp16.h>
#include <stdint.h>

#define T_TOK 2048
#define KDIM  2048
#define IDIM  1024
#define NEXP  8
#define NJOBS 9
#define CAP   4096
#define TOPK  2

#define A_STRIDE 72
#define B_STRIDE 136
#define ABUF (128 * A_STRIDE * 2)          // 18432 B per stage
#define BBUF (64 * B_STRIDE * 2)           // 17408 B per stage
#define BOFF (3 * ABUF)                    // 55296
#define TSOFF (BOFF + 3 * BBUF)            // 107520
#define DSMEM (TSOFF + 512)                // 108032

// ---------------- scratch (device globals) ----------------
__device__ int   g_cnt[NJOBS];
__device__ int   g_tok[NJOBS * CAP];
__device__ int   g_slot[T_TOK * TOPK];
__device__ __align__(16) __half g_xh[(size_t)T_TOK * KDIM];                 // [t][k]
__device__ __align__(16) __half g_wgu[(size_t)NJOBS * KDIM * 2 * IDIM];     // [job][k][2I]
__device__ __align__(16) __half g_wd [(size_t)NJOBS * IDIM * KDIM];         // [job][i][K]
__device__ __align__(16) __half g_acth[(size_t)NJOBS * CAP * IDIM];         // [job][slot][i]
__device__ __align__(16) __half g_y[(size_t)NJOBS * CAP * KDIM];            // [slot][k] fp16

// ---------------- helpers ----------------
__device__ __forceinline__ uint32_t sptr(const void* p) {
    return (uint32_t)__cvta_generic_to_shared(p);
}
__device__ __forceinline__ void cp16(uint32_t dst, const void* src) {
    asm volatile("cp.async.cg.shared.global [%0], [%1], 16;" :: "r"(dst), "l"(src));
}
__device__ __forceinline__ void cpcommit() { asm volatile("cp.async.commit_group;"); }
__device__ __forceinline__ void cpwait1()  { asm volatile("cp.async.wait_group 1;"); }
__device__ __forceinline__ void cpwait0()  { asm volatile("cp.async.wait_group 0;"); }

__device__ __forceinline__ void ldsm4(uint32_t* r, uint32_t a) {
    asm volatile("ldmatrix.sync.aligned.m8n8.x4.shared.b16 {%0,%1,%2,%3}, [%4];"
        : "=r"(r[0]), "=r"(r[1]), "=r"(r[2]), "=r"(r[3]) : "r"(a));
}
__device__ __forceinline__ void ldsm4t(uint32_t* r, uint32_t a) {
    asm volatile("ldmatrix.sync.aligned.m8n8.x4.trans.shared.b16 {%0,%1,%2,%3}, [%4];"
        : "=r"(r[0]), "=r"(r[1]), "=r"(r[2]), "=r"(r[3]) : "r"(a));
}
__device__ __forceinline__ void mma16816(float* d, const uint32_t* a, uint32_t b0, uint32_t b1) {
    asm volatile("mma.sync.aligned.m16n8k16.row.col.f32.f16.f16.f32 "
        "{%0,%1,%2,%3},{%4,%5,%6,%7},{%8,%9},{%0,%1,%2,%3};"
        : "+f"(d[0]), "+f"(d[1]), "+f"(d[2]), "+f"(d[3])
        : "r"(a[0]), "r"(a[1]), "r"(a[2]), "r"(a[3]), "r"(b0), "r"(b1));
}

// ---------------- small kernels ----------------
__global__ void k_route(const int* __restrict__ ids) {
    int t = blockIdx.x * 256 + threadIdx.x;
    for (int s = 0; s < TOPK; s++) {
        int e   = ids[t * TOPK + s];
        int pos = atomicAdd(&g_cnt[e], 1);
        int slot = e * CAP + pos;
        g_tok[slot] = t;
        g_slot[t * TOPK + s] = slot;
    }
    g_tok[NEXP * CAP + t] = t;
    if (t == 0) g_cnt[NEXP] = T_TOK;
}

__global__ void k_x2h(const float* __restrict__ x) {
    int i = blockIdx.x * 256 + threadIdx.x;
    g_xh[i] = __float2half_rn(x[i]);
}

// ---------------- kernel: dequant, both weight sets in one launch ----------
// blockIdx.z: 0 = gate_up (Kd=KDIM, Nd=2I), 1 = down (Kd=IDIM, Nd=KDIM).
// Thread owns (kw, 8 n-cols); 8 STG.128 per thread. Numerics as before.
__global__ __launch_bounds__(256) void k_dq(
    const int* __restrict__ gup, const float* __restrict__ gus,
    const int* __restrict__ sgup, const float* __restrict__ sgus,
    const int* __restrict__ dwp, const float* __restrict__ dws,
    const int* __restrict__ sdp, const float* __restrict__ sds,
    __half* __restrict__ wgu, __half* __restrict__ wd)
{
    const int set = blockIdx.z;
    const int Kd  = set ? IDIM : KDIM;
    const int Nd  = set ? KDIM : (2 * IDIM);
    const int nblk = (Kd >> 3) * (Nd >> 3) / 256;
    if (blockIdx.x >= nblk) return;

    const int job = blockIdx.y;
    const int* W; const float* Sc; __half* O;
    if (set == 0) {
        if (job < NEXP) {
            W  = gup + (size_t)job * (Kd >> 3) * Nd;
            Sc = gus + (size_t)job * (Kd >> 6) * Nd;
        } else { W = sgup; Sc = sgus; }
        O = wgu + (size_t)job * Kd * Nd;
    } else {
        if (job < NEXP) {
            W  = dwp + (size_t)job * (Kd >> 3) * Nd;
            Sc = dws + (size_t)job * (Kd >> 6) * Nd;
        } else { W = sdp; Sc = sds; }
        O = wd + (size_t)job * Kd * Nd;
    }

    const int g  = blockIdx.x * 256 + threadIdx.x;
    const int oN = Nd >> 3;
    const int kw = g / oN;
    const int n  = (g - kw * oN) * 8;

    const int4 wv0 = *(const int4*)(W + (size_t)kw * Nd + n);
    const int4 wv1 = *(const int4*)(W + (size_t)kw * Nd + n + 4);
    const float4 sv0 = *(const float4*)(Sc + (size_t)(kw >> 3) * Nd + n);
    const float4 sv1 = *(const float4*)(Sc + (size_t)(kw >> 3) * Nd + n + 4);
    const float s0 = sv0.x * 16384.0f, s1 = sv0.y * 16384.0f;
    const float s2 = sv0.z * 16384.0f, s3 = sv0.w * 16384.0f;
    const float s4 = sv1.x * 16384.0f, s5 = sv1.y * 16384.0f;
    const float s6 = sv1.z * 16384.0f, s7 = sv1.w * 16384.0f;
    const uint32_t w0 = (uint32_t)wv0.x, w1 = (uint32_t)wv0.y;
    const uint32_t w2 = (uint32_t)wv0.z, w3 = (uint32_t)wv0.w;
    const uint32_t w4 = (uint32_t)wv1.x, w5 = (uint32_t)wv1.y;
    const uint32_t w6 = (uint32_t)wv1.z, w7 = (uint32_t)wv1.w;

    __half* orow = O + (size_t)(kw * 8) * Nd + n;
    #pragma unroll
    for (int k = 0; k < 8; k++) {
        uint32_t u0 = ((w0 >> (4 * k)) & 0xFu) | (((w1 >> (4 * k)) & 0xFu) << 16);
        uint32_t u1 = ((w2 >> (4 * k)) & 0xFu) | (((w3 >> (4 * k)) & 0xFu) << 16);
        uint32_t u2 = ((w4 >> (4 * k)) & 0xFu) | (((w5 >> (4 * k)) & 0xFu) << 16);
        uint32_t u3 = ((w6 >> (4 * k)) & 0xFu) | (((w7 >> (4 * k)) & 0xFu) << 16);
        uint32_t h0 = ((u0 & 0x00070007u) << 9) | ((u0 & 0x00080008u) << 12);
        uint32_t h1 = ((u1 & 0x00070007u) << 9) | ((u1 & 0x00080008u) << 12);
        uint32_t h2 = ((u2 & 0x00070007u) << 9) | ((u2 & 0x00080008u) << 12);
        uint32_t h3 = ((u3 & 0x00070007u) << 9) | ((u3 & 0x00080008u) << 12);
        float2 f0 = __half22float2(*reinterpret_cast<__half2*>(&h0));
        float2 f1 = __half22float2(*reinterpret_cast<__half2*>(&h1));
        float2 f2 = __half22float2(*reinterpret_cast<__half2*>(&h2));
        float2 f3 = __half22float2(*reinterpret_cast<__half2*>(&h3));
        __half2 r0 = __floats2half2_rn(f0.x * s0, f0.y * s1);
        __half2 r1 = __floats2half2_rn(f1.x * s2, f1.y * s3);
        __half2 r2 = __floats2half2_rn(f2.x * s4, f2.y * s5);
        __half2 r3 = __floats2half2_rn(f3.x * s6, f3.y * s7);
        uint4 st;
        st.x = *reinterpret_cast<uint32_t*>(&r0);
        st.y = *reinterpret_cast<uint32_t*>(&r1);
        st.z = *reinterpret_cast<uint32_t*>(&r2);
        st.w = *reinterpret_cast<uint32_t*>(&r3);
        *(uint4*)(orow + (size_t)k * Nd) = st;
    }
}

// ---------------- kernel: gate_up HMMA GEMM + silu (R13 proven) ----------
// 256 threads = 8 warps (4m x 2n). M=128, tile cols 128 (64 gate | 64 up),
// BK=64, 3-stage cp.async.
__global__ __launch_bounds__(256) void k_gemm1() {
    extern __shared__ __align__(16) char sm[];
    int* ts = (int*)(sm + TSOFF);

    const int job  = blockIdx.z;
    const int cnt  = g_cnt[job];
    const int base = blockIdx.x * 128;
    if (base >= cnt) return;

    const int n0   = blockIdx.y * 64;
    const int tid  = threadIdx.x;
    const int lane = tid & 31;
    const int warp = tid >> 5;
    const int wm   = (warp >> 1) * 32;
    const int wn   = (warp & 1) * 64;
    const int pair = warp & 1;
    const __half* Wj = g_wgu + (size_t)job * KDIM * (2 * IDIM);

    if (tid < 128) {
        int p = base + tid;
        ts[tid] = (p < cnt) ? g_tok[job * CAP + p] : 0;
    }
    __syncthreads();

    int arow[4], aseg[4], atok[4], aoff[4];
    for (int i = 0; i < 4; i++) {
        int c   = tid + i * 256;
        arow[i] = c >> 3;
        aseg[i] = c & 7;
        atok[i] = ts[arow[i]];
        aoff[i] = (arow[i] * A_STRIDE + aseg[i] * 8) * 2;
    }
    int bkr[4], boff[4], bgc[4];
    for (int i = 0; i < 4; i++) {
        int c   = tid + i * 256;
        bkr[i]  = c >> 4;
        int seg = c & 15;
        boff[i] = (bkr[i] * B_STRIDE + seg * 8) * 2;
        int p2  = seg >> 3;
        int sub = (seg & 7) * 8;
        bgc[i]  = (sub < 32) ? (n0 + p2 * 32 + sub)
                             : (IDIM + n0 + p2 * 32 + (sub - 32));
    }

    const uint32_t asb = sptr(sm);
    const uint32_t bsb = asb + BOFF;
    const uint32_t a_frag = asb + ((wm + (lane & 15)) * A_STRIDE + (lane >> 4) * 8) * 2;
    const uint32_t b_frag = bsb + ((lane & 15) * B_STRIDE + wn + (lane >> 4) * 8) * 2;

    float acc[2][8][4];
    for (int i = 0; i < 2; i++)
        for (int j = 0; j < 8; j++)
            for (int k = 0; k < 4; k++) acc[i][j][k] = 0.f;

    auto fill = [&](int c, int buf) {
        int kc = c * 64;
        for (int i = 0; i < 4; i++)
            cp16(asb + buf * ABUF + aoff[i],
                 g_xh + (size_t)atok[i] * KDIM + kc + aseg[i] * 8);
        for (int i = 0; i < 4; i++)
            cp16(bsb + buf * BBUF + boff[i],
                 Wj + (size_t)(kc + bkr[i]) * (2 * IDIM) + bgc[i]);
        cpcommit();
    };

    fill(0, 0);
    fill(1, 1);

    const int C = KDIM / 64;
    for (int c = 0; c < C; c++) {
        if (c >= C - 1) cpwait0(); else cpwait1();
        __syncthreads();
        if (c + 2 < C) fill(c + 2, (c + 2) % 3);
        int buf = c % 3;
        uint32_t ab = a_frag + buf * ABUF;
        uint32_t bb = b_frag + buf * BBUF;
        for (int ks = 0; ks < 4; ks++) {
            uint32_t a0[4], a1[4];
            ldsm4(a0, ab + ks * 32);
            ldsm4(a1, ab + ks * 32 + 16 * A_STRIDE * 2);
            for (int jp = 0; jp < 4; jp++) {
                uint32_t b[4];
                ldsm4t(b, bb + jp * 32 + ks * (16 * B_STRIDE * 2));
                mma16816(acc[0][jp * 2 + 0], a0, b[0], b[1]);
                mma16816(acc[1][jp * 2 + 0], a1, b[0], b[1]);
                mma16816(acc[0][jp * 2 + 1], a0, b[2], b[3]);
                mma16816(acc[1][jp * 2 + 1], a1, b[2], b[3]);
            }
        }
    }

    __half* actb = g_acth + (size_t)job * CAP * IDIM;
    for (int am = 0; am < 2; am++) {
        for (int h = 0; h < 2; h++) {
            int r   = wm + am * 16 + (lane >> 2) + h * 8;
            int pos = base + r;
            if (pos >= cnt) continue;
            __half* orow = actb + (size_t)pos * IDIM;
            for (int jp = 0; jp < 2; jp++) {
                for (int jj = 0; jj < 2; jj++) {
                    float g0 = acc[am][jp * 2 + jj][h * 2 + 0];
                    float g1 = acc[am][jp * 2 + jj][h * 2 + 1];
                    float u0 = acc[am][(jp + 2) * 2 + jj][h * 2 + 0];
                    float u1 = acc[am][(jp + 2) * 2 + jj][h * 2 + 1];
                    float o0 = g0 / (1.0f + __expf(-g0)) * u0;
                    float o1 = g1 / (1.0f + __expf(-g1)) * u1;
                    int col = n0 + pair * 32 + jp * 16 + jj * 8 + (lane & 3) * 2;
                    *(__half2*)(orow + col) = __floats2half2_rn(o0, o1);
                }
            }
        }
    }
}

// ---------------- kernel: down HMMA GEMM -> g_y (fp16) (R13 proven) -------
__global__ __launch_bounds__(256) void k_gemm2() {
    extern __shared__ __align__(16) char sm[];

    const int job  = blockIdx.z;
    const int cnt  = g_cnt[job];
    const int base = blockIdx.x * 128;
    if (base >= cnt) return;

    const int n0   = blockIdx.y * 128;
    const int tid  = threadIdx.x;
    const int lane = tid & 31;
    const int warp = tid >> 5;
    const int wm   = (warp >> 1) * 32;
    const int wn   = (warp & 1) * 64;
    const __half* Wj = g_wd + (size_t)job * IDIM * KDIM;
    const __half* Ab = g_acth + (size_t)job * CAP * IDIM;

    int arow[4], aseg[4], aoff[4];
    for (int i = 0; i < 4; i++) {
        int c   = tid + i * 256;
        arow[i] = c >> 3;
        aseg[i] = c & 7;
        aoff[i] = (arow[i] * A_STRIDE + aseg[i] * 8) * 2;
    }
    int bkr[4], boff[4], bgc[4];
    for (int i = 0; i < 4; i++) {
        int c   = tid + i * 256;
        bkr[i]  = c >> 4;
        int seg = c & 15;
        boff[i] = (bkr[i] * B_STRIDE + seg * 8) * 2;
        bgc[i]  = n0 + seg * 8;
    }

    const uint32_t asb = sptr(sm);
    const uint32_t bsb = asb + BOFF;
    const uint32_t a_frag = asb + ((wm + (lane & 15)) * A_STRIDE + (lane >> 4) * 8) * 2;
    const uint32_t b_frag = bsb + ((lane & 15) * B_STRIDE + wn + (lane >> 4) * 8) * 2;

    float acc[2][8][4];
    for (int i = 0; i < 2; i++)
        for (int j = 0; j < 8; j++)
            for (int k = 0; k < 4; k++) acc[i][j][k] = 0.f;

    auto fill = [&](int c, int buf) {
        int kc = c * 64;
        for (int i = 0; i < 4; i++)
            cp16(asb + buf * ABUF + aoff[i],
                 Ab + (size_t)(base + arow[i]) * IDIM + kc + aseg[i] * 8);
        for (int i = 0; i < 4; i++)
            cp16(bsb + buf * BBUF + boff[i],
                 Wj + (size_t)(kc + bkr[i]) * KDIM + bgc[i]);
        cpcommit();
    };

    fill(0, 0);
    fill(1, 1);

    const int C = IDIM / 64;
    for (int c = 0; c < C; c++) {
        if (c >= C - 1) cpwait0(); else cpwait1();
        __syncthreads();
        if (c + 2 < C) fill(c + 2, (c + 2) % 3);
        int buf = c % 3;
        uint32_t ab = a_frag + buf * ABUF;
        uint32_t bb = b_frag + buf * BBUF;
        for (int ks = 0; ks < 4; ks++) {
            uint32_t a0[4], a1[4];
            ldsm4(a0, ab + ks * 32);
            ldsm4(a1, ab + ks * 32 + 16 * A_STRIDE * 2);
            for (int jp = 0; jp < 4; jp++) {
                uint32_t b[4];
                ldsm4t(b, bb + jp * 32 + ks * (16 * B_STRIDE * 2));
                mma16816(acc[0][jp * 2 + 0], a0, b[0], b[1]);
                mma16816(acc[1][jp * 2 + 0], a1, b[0], b[1]);
                mma16816(acc[0][jp * 2 + 1], a0, b[2], b[3]);
                mma16816(acc[1][jp * 2 + 1], a1, b[2], b[3]);
            }
        }
    }

    __half* yb = g_y + (size_t)job * CAP * KDIM;
    for (int am = 0; am < 2; am++) {
        for (int h = 0; h < 2; h++) {
            int r   = wm + am * 16 + (lane >> 2) + h * 8;
            int pos = base + r;
            if (pos >= cnt) continue;
            __half* orow = yb + (size_t)pos * KDIM;
            for (int j = 0; j < 8; j++) {
                int col = n0 + wn + (j >> 1) * 16 + (j & 1) * 8 + (lane & 3) * 2;
                *(__half2*)(orow + col) =
                    __floats2half2_rn(acc[am][j][h * 2 + 0], acc[am][j][h * 2 + 1]);
            }
        }
    }
}

// ---------------- kernel: combine routed + shared -> out; reset counters ----
__global__ __launch_bounds__(256) void k_combine(float* __restrict__ out,
                                                 const float* __restrict__ probs) {
    const int t = blockIdx.x;
    const uint4* y0 = (const uint4*)(g_y + (size_t)g_slot[t * TOPK + 0] * KDIM);
    const uint4* y1 = (const uint4*)(g_y + (size_t)g_slot[t * TOPK + 1] * KDIM);
    const uint4* ys = (const uint4*)(g_y + (size_t)(NEXP * CAP + t) * KDIM);
    const float p0 = probs[t * TOPK + 0];
    const float p1 = probs[t * TOPK + 1];
    float4* o = (float4*)(out + (size_t)t * KDIM);
    const int i = threadIdx.x;
    uint4 a = y0[i], b = y1[i], s = ys[i];
    const uint32_t* ap = (const uint32_t*)&a;
    const uint32_t* bp = (const uint32_t*)&b;
    const uint32_t* sp = (const uint32_t*)&s;
    float4 r0, r1;
    for (int j = 0; j < 4; j++) {
        float2 fa = __half22float2(*(const __half2*)&ap[j]);
        float2 fb = __half22float2(*(const __half2*)&bp[j]);
        float2 fs = __half22float2(*(const __half2*)&sp[j]);
        float* dst = (j < 2) ? ((float*)&r0 + j * 2) : ((float*)&r1 + (j - 2) * 2);
        dst[0] = p0 * fa.x + p1 * fb.x + fs.x;
        dst[1] = p0 * fa.y + p1 * fb.y + fs.y;
    }
    o[i * 2]     = r0;
    o[i * 2 + 1] = r1;
    if (blockIdx.x == 0 && threadIdx.x < NJOBS) g_cnt[threadIdx.x] = 0;
}

// ---------------- launcher ----------------
extern "C" void kernel_launch(void* const* d_in, const int* in_sizes, int n_in,
                              void* d_out, int out_size) {
    const float* x     = (const float*)d_in[0];
    const int*   gup   = (const int*)  d_in[1];
    const float* gus   = (const float*)d_in[2];
    const int*   dwp   = (const int*)  d_in[3];
    const float* dws   = (const float*)d_in[4];
    const int*   sgup  = (const int*)  d_in[5];
    const float* sgus  = (const float*)d_in[6];
    const int*   sdp   = (const int*)  d_in[7];
    const float* sds   = (const float*)d_in[8];
    const int*   ids   = (const int*)  d_in[9];
    const float* probs = (const float*)d_in[10];
    float* out = (float*)d_out;

    cudaFuncSetAttribute(k_gemm1, cudaFuncAttributeMaxDynamicSharedMemorySize, DSMEM);
    cudaFuncSetAttribute(k_gemm2, cudaFuncAttributeMaxDynamicSharedMemorySize, DSMEM);

    __half* wgu;
    __half* wd;
    cudaGetSymbolAddress((void**)&wgu, g_wgu);
    cudaGetSymbolAddress((void**)&wd,  g_wd);

    // Launch order keeps k_gemm1 at profile slot #4.
    k_x2h  <<<(T_TOK * KDIM) / 256, 256>>>(x);                                  // 1
    k_route<<<T_TOK / 256, 256>>>(ids);                                         // 2
    k_dq<<<dim3(256, NJOBS, 2), 256>>>(gup, gus, sgup, sgus,                    // 3
                                       dwp, dws, sdp, sds, wgu, wd);
    k_gemm1<<<dim3(CAP / 128, IDIM / 64, NJOBS), 256, DSMEM>>>();               // 4
    k_gemm2<<<dim3(CAP / 128, KDIM / 128, NJOBS), 256, DSMEM>>>();              // 5
    k_combine<<<T_TOK, 256>>>(out, probs);                                      // 6
}

// round 16
// speedup vs baseline: 1.4944x; 1.0064x over previous
#include <cuda_runtime.h>
#include <cuda_fp16.h>
#include <stdint.h>

#define T_TOK 2048
#define KDIM  2048
#define IDIM  1024
#define NEXP  8
#define NJOBS 9
#define CAP   4096
#define TOPK  2

#define A_STRIDE 72
#define B_STRIDE 136
#define ABUF (128 * A_STRIDE * 2)          // 18432 B per stage
#define BBUF (64 * B_STRIDE * 2)           // 17408 B per stage
#define BOFF (3 * ABUF)                    // 55296
#define TSOFF (BOFF + 3 * BBUF)            // 107520
#define DSMEM (TSOFF + 512)                // 108032

// ---------------- scratch (device globals) ----------------
__device__ int   g_cnt[NJOBS];
__device__ int   g_tok[NJOBS * CAP];
__device__ int   g_slot[T_TOK * TOPK];
__device__ __align__(16) __half g_xh[(size_t)T_TOK * KDIM];                 // [t][k]
__device__ __align__(16) __half g_wgu[(size_t)NJOBS * KDIM * 2 * IDIM];     // [job][k][2I]
__device__ __align__(16) __half g_wd [(size_t)NJOBS * IDIM * KDIM];         // [job][i][K]
__device__ __align__(16) __half g_acth[(size_t)NJOBS * CAP * IDIM];         // [job][slot][i]
__device__ __align__(16) __half g_y[(size_t)NJOBS * CAP * KDIM];            // [slot][k] fp16

// ---------------- helpers ----------------
__device__ __forceinline__ uint32_t sptr(const void* p) {
    return (uint32_t)__cvta_generic_to_shared(p);
}
__device__ __forceinline__ void cp16(uint32_t dst, const void* src) {
    asm volatile("cp.async.cg.shared.global [%0], [%1], 16;" :: "r"(dst), "l"(src));
}
__device__ __forceinline__ void cpcommit() { asm volatile("cp.async.commit_group;"); }
__device__ __forceinline__ void cpwait1()  { asm volatile("cp.async.wait_group 1;"); }
__device__ __forceinline__ void cpwait0()  { asm volatile("cp.async.wait_group 0;"); }

__device__ __forceinline__ void ldsm4(uint32_t* r, uint32_t a) {
    asm volatile("ldmatrix.sync.aligned.m8n8.x4.shared.b16 {%0,%1,%2,%3}, [%4];"
        : "=r"(r[0]), "=r"(r[1]), "=r"(r[2]), "=r"(r[3]) : "r"(a));
}
__device__ __forceinline__ void ldsm4t(uint32_t* r, uint32_t a) {
    asm volatile("ldmatrix.sync.aligned.m8n8.x4.trans.shared.b16 {%0,%1,%2,%3}, [%4];"
        : "=r"(r[0]), "=r"(r[1]), "=r"(r[2]), "=r"(r[3]) : "r"(a));
}
__device__ __forceinline__ void mma16816(float* d, const uint32_t* a, uint32_t b0, uint32_t b1) {
    asm volatile("mma.sync.aligned.m16n8k16.row.col.f32.f16.f16.f32 "
        "{%0,%1,%2,%3},{%4,%5,%6,%7},{%8,%9},{%0,%1,%2,%3};"
        : "+f"(d[0]), "+f"(d[1]), "+f"(d[2]), "+f"(d[3])
        : "r"(a[0]), "r"(a[1]), "r"(a[2]), "r"(a[3]), "r"(b0), "r"(b1));
}

// ---------------- small kernels ----------------
__global__ void k_route(const int* __restrict__ ids) {
    int t = blockIdx.x * 256 + threadIdx.x;
    for (int s = 0; s < TOPK; s++) {
        int e   = ids[t * TOPK + s];
        int pos = atomicAdd(&g_cnt[e], 1);
        int slot = e * CAP + pos;
        g_tok[slot] = t;
        g_slot[t * TOPK + s] = slot;
    }
    g_tok[NEXP * CAP + t] = t;
    if (t == 0) g_cnt[NEXP] = T_TOK;
}

__global__ void k_x2h(const float* __restrict__ x) {
    int i = blockIdx.x * 256 + threadIdx.x;
    g_xh[i] = __float2half_rn(x[i]);
}

// ---------------- kernel: dequant, both weight sets in one launch ----------
__global__ __launch_bounds__(256) void k_dq(
    const int* __restrict__ gup, const float* __restrict__ gus,
    const int* __restrict__ sgup, const float* __restrict__ sgus,
    const int* __restrict__ dwp, const float* __restrict__ dws,
    const int* __restrict__ sdp, const float* __restrict__ sds,
    __half* __restrict__ wgu, __half* __restrict__ wd)
{
    const int set = blockIdx.z;
    const int Kd  = set ? IDIM : KDIM;
    const int Nd  = set ? KDIM : (2 * IDIM);
    const int nblk = (Kd >> 3) * (Nd >> 3) / 256;
    if (blockIdx.x >= nblk) return;

    const int job = blockIdx.y;
    const int* W; const float* Sc; __half* O;
    if (set == 0) {
        if (job < NEXP) {
            W  = gup + (size_t)job * (Kd >> 3) * Nd;
            Sc = gus + (size_t)job * (Kd >> 6) * Nd;
        } else { W = sgup; Sc = sgus; }
        O = wgu + (size_t)job * Kd * Nd;
    } else {
        if (job < NEXP) {
            W  = dwp + (size_t)job * (Kd >> 3) * Nd;
            Sc = dws + (size_t)job * (Kd >> 6) * Nd;
        } else { W = sdp; Sc = sds; }
        O = wd + (size_t)job * Kd * Nd;
    }

    const int g  = blockIdx.x * 256 + threadIdx.x;
    const int oN = Nd >> 3;
    const int kw = g / oN;
    const int n  = (g - kw * oN) * 8;

    const int4 wv0 = *(const int4*)(W + (size_t)kw * Nd + n);
    const int4 wv1 = *(const int4*)(W + (size_t)kw * Nd + n + 4);
    const float4 sv0 = *(const float4*)(Sc + (size_t)(kw >> 3) * Nd + n);
    const float4 sv1 = *(const float4*)(Sc + (size_t)(kw >> 3) * Nd + n + 4);
    const float s0 = sv0.x * 16384.0f, s1 = sv0.y * 16384.0f;
    const float s2 = sv0.z * 16384.0f, s3 = sv0.w * 16384.0f;
    const float s4 = sv1.x * 16384.0f, s5 = sv1.y * 16384.0f;
    const float s6 = sv1.z * 16384.0f, s7 = sv1.w * 16384.0f;
    const uint32_t w0 = (uint32_t)wv0.x, w1 = (uint32_t)wv0.y;
    const uint32_t w2 = (uint32_t)wv0.z, w3 = (uint32_t)wv0.w;
    const uint32_t w4 = (uint32_t)wv1.x, w5 = (uint32_t)wv1.y;
    const uint32_t w6 = (uint32_t)wv1.z, w7 = (uint32_t)wv1.w;

    __half* orow = O + (size_t)(kw * 8) * Nd + n;
    #pragma unroll
    for (int k = 0; k < 8; k++) {
        uint32_t u0 = ((w0 >> (4 * k)) & 0xFu) | (((w1 >> (4 * k)) & 0xFu) << 16);
        uint32_t u1 = ((w2 >> (4 * k)) & 0xFu) | (((w3 >> (4 * k)) & 0xFu) << 16);
        uint32_t u2 = ((w4 >> (4 * k)) & 0xFu) | (((w5 >> (4 * k)) & 0xFu) << 16);
        uint32_t u3 = ((w6 >> (4 * k)) & 0xFu) | (((w7 >> (4 * k)) & 0xFu) << 16);
        uint32_t h0 = ((u0 & 0x00070007u) << 9) | ((u0 & 0x00080008u) << 12);
        uint32_t h1 = ((u1 & 0x00070007u) << 9) | ((u1 & 0x00080008u) << 12);
        uint32_t h2 = ((u2 & 0x00070007u) << 9) | ((u2 & 0x00080008u) << 12);
        uint32_t h3 = ((u3 & 0x00070007u) << 9) | ((u3 & 0x00080008u) << 12);
        float2 f0 = __half22float2(*reinterpret_cast<__half2*>(&h0));
        float2 f1 = __half22float2(*reinterpret_cast<__half2*>(&h1));
        float2 f2 = __half22float2(*reinterpret_cast<__half2*>(&h2));
        float2 f3 = __half22float2(*reinterpret_cast<__half2*>(&h3));
        __half2 r0 = __floats2half2_rn(f0.x * s0, f0.y * s1);
        __half2 r1 = __floats2half2_rn(f1.x * s2, f1.y * s3);
        __half2 r2 = __floats2half2_rn(f2.x * s4, f2.y * s5);
        __half2 r3 = __floats2half2_rn(f3.x * s6, f3.y * s7);
        uint4 st;
        st.x = *reinterpret_cast<uint32_t*>(&r0);
        st.y = *reinterpret_cast<uint32_t*>(&r1);
        st.z = *reinterpret_cast<uint32_t*>(&r2);
        st.w = *reinterpret_cast<uint32_t*>(&r3);
        *(uint4*)(orow + (size_t)k * Nd) = st;
    }
}

// ---------------- kernel: gate_up HMMA GEMM + silu ----------
// 256 threads = 8 warps (4m x 2n). M=128, tile cols 128 (64 gate | 64 up),
// BK=64, 3-stage cp.async. Inner loop: batch all ldsm, then all mma.
__global__ __launch_bounds__(256) void k_gemm1() {
    extern __shared__ __align__(16) char sm[];
    int* ts = (int*)(sm + TSOFF);

    const int job  = blockIdx.z;
    const int cnt  = g_cnt[job];
    const int base = blockIdx.x * 128;
    if (base >= cnt) return;

    const int n0   = blockIdx.y * 64;
    const int tid  = threadIdx.x;
    const int lane = tid & 31;
    const int warp = tid >> 5;
    const int wm   = (warp >> 1) * 32;
    const int wn   = (warp & 1) * 64;
    const int pair = warp & 1;
    const __half* Wj = g_wgu + (size_t)job * KDIM * (2 * IDIM);

    if (tid < 128) {
        int p = base + tid;
        ts[tid] = (p < cnt) ? g_tok[job * CAP + p] : 0;
    }
    __syncthreads();

    int arow[4], aseg[4], atok[4], aoff[4];
    for (int i = 0; i < 4; i++) {
        int c   = tid + i * 256;
        arow[i] = c >> 3;
        aseg[i] = c & 7;
        atok[i] = ts[arow[i]];
        aoff[i] = (arow[i] * A_STRIDE + aseg[i] * 8) * 2;
    }
    int bkr[4], boff[4], bgc[4];
    for (int i = 0; i < 4; i++) {
        int c   = tid + i * 256;
        bkr[i]  = c >> 4;
        int seg = c & 15;
        boff[i] = (bkr[i] * B_STRIDE + seg * 8) * 2;
        int p2  = seg >> 3;
        int sub = (seg & 7) * 8;
        bgc[i]  = (sub < 32) ? (n0 + p2 * 32 + sub)
                             : (IDIM + n0 + p2 * 32 + (sub - 32));
    }

    const uint32_t asb = sptr(sm);
    const uint32_t bsb = asb + BOFF;
    const uint32_t a_frag = asb + ((wm + (lane & 15)) * A_STRIDE + (lane >> 4) * 8) * 2;
    const uint32_t b_frag = bsb + ((lane & 15) * B_STRIDE + wn + (lane >> 4) * 8) * 2;

    float acc[2][8][4];
    for (int i = 0; i < 2; i++)
        for (int j = 0; j < 8; j++)
            for (int k = 0; k < 4; k++) acc[i][j][k] = 0.f;

    auto fill = [&](int c, int buf) {
        int kc = c * 64;
        for (int i = 0; i < 4; i++)
            cp16(asb + buf * ABUF + aoff[i],
                 g_xh + (size_t)atok[i] * KDIM + kc + aseg[i] * 8);
        for (int i = 0; i < 4; i++)
            cp16(bsb + buf * BBUF + boff[i],
                 Wj + (size_t)(kc + bkr[i]) * (2 * IDIM) + bgc[i]);
        cpcommit();
    };

    fill(0, 0);
    fill(1, 1);

    const int C = KDIM / 64;
    for (int c = 0; c < C; c++) {
        if (c >= C - 1) cpwait0(); else cpwait1();
        __syncthreads();
        if (c + 2 < C) fill(c + 2, (c + 2) % 3);
        int buf = c % 3;
        uint32_t ab = a_frag + buf * ABUF;
        uint32_t bb = b_frag + buf * BBUF;
        #pragma unroll
        for (int ks = 0; ks < 4; ks++) {
            uint32_t a0[4], a1[4], b[4][4];
            ldsm4(a0, ab + ks * 32);
            ldsm4(a1, ab + ks * 32 + 16 * A_STRIDE * 2);
            #pragma unroll
            for (int jp = 0; jp < 4; jp++)
                ldsm4t(b[jp], bb + jp * 32 + ks * (16 * B_STRIDE * 2));
            #pragma unroll
            for (int jp = 0; jp < 4; jp++) {
                mma16816(acc[0][jp * 2 + 0], a0, b[jp][0], b[jp][1]);
                mma16816(acc[1][jp * 2 + 0], a1, b[jp][0], b[jp][1]);
                mma16816(acc[0][jp * 2 + 1], a0, b[jp][2], b[jp][3]);
                mma16816(acc[1][jp * 2 + 1], a1, b[jp][2], b[jp][3]);
            }
        }
    }

    __half* actb = g_acth + (size_t)job * CAP * IDIM;
    for (int am = 0; am < 2; am++) {
        for (int h = 0; h < 2; h++) {
            int r   = wm + am * 16 + (lane >> 2) + h * 8;
            int pos = base + r;
            if (pos >= cnt) continue;
            __half* orow = actb + (size_t)pos * IDIM;
            for (int jp = 0; jp < 2; jp++) {
                for (int jj = 0; jj < 2; jj++) {
                    float g0 = acc[am][jp * 2 + jj][h * 2 + 0];
                    float g1 = acc[am][jp * 2 + jj][h * 2 + 1];
                    float u0 = acc[am][(jp + 2) * 2 + jj][h * 2 + 0];
                    float u1 = acc[am][(jp + 2) * 2 + jj][h * 2 + 1];
                    float o0 = g0 / (1.0f + __expf(-g0)) * u0;
                    float o1 = g1 / (1.0f + __expf(-g1)) * u1;
                    int col = n0 + pair * 32 + jp * 16 + jj * 8 + (lane & 3) * 2;
                    *(__half2*)(orow + col) = __floats2half2_rn(o0, o1);
                }
            }
        }
    }
}

// ---------------- kernel: down HMMA GEMM -> g_y (fp16) -------
__global__ __launch_bounds__(256) void k_gemm2() {
    extern __shared__ __align__(16) char sm[];

    const int job  = blockIdx.z;
    const int cnt  = g_cnt[job];
    const int base = blockIdx.x * 128;
    if (base >= cnt) return;

    const int n0   = blockIdx.y * 128;
    const int tid  = threadIdx.x;
    const int lane = tid & 31;
    const int warp = tid >> 5;
    const int wm   = (warp >> 1) * 32;
    const int wn   = (warp & 1) * 64;
    const __half* Wj = g_wd + (size_t)job * IDIM * KDIM;
    const __half* Ab = g_acth + (size_t)job * CAP * IDIM;

    int arow[4], aseg[4], aoff[4];
    for (int i = 0; i < 4; i++) {
        int c   = tid + i * 256;
        arow[i] = c >> 3;
        aseg[i] = c & 7;
        aoff[i] = (arow[i] * A_STRIDE + aseg[i] * 8) * 2;
    }
    int bkr[4], boff[4], bgc[4];
    for (int i = 0; i < 4; i++) {
        int c   = tid + i * 256;
        bkr[i]  = c >> 4;
        int seg = c & 15;
        boff[i] = (bkr[i] * B_STRIDE + seg * 8) * 2;
        bgc[i]  = n0 + seg * 8;
    }

    const uint32_t asb = sptr(sm);
    const uint32_t bsb = asb + BOFF;
    const uint32_t a_frag = asb + ((wm + (lane & 15)) * A_STRIDE + (lane >> 4) * 8) * 2;
    const uint32_t b_frag = bsb + ((lane & 15) * B_STRIDE + wn + (lane >> 4) * 8) * 2;

    float acc[2][8][4];
    for (int i = 0; i < 2; i++)
        for (int j = 0; j < 8; j++)
            for (int k = 0; k < 4; k++) acc[i][j][k] = 0.f;

    auto fill = [&](int c, int buf) {
        int kc = c * 64;
        for (int i = 0; i < 4; i++)
            cp16(asb + buf * ABUF + aoff[i],
                 Ab + (size_t)(base + arow[i]) * IDIM + kc + aseg[i] * 8);
        for (int i = 0; i < 4; i++)
            cp16(bsb + buf * BBUF + boff[i],
                 Wj + (size_t)(kc + bkr[i]) * KDIM + bgc[i]);
        cpcommit();
    };

    fill(0, 0);
    fill(1, 1);

    const int C = IDIM / 64;
    for (int c = 0; c < C; c++) {
        if (c >= C - 1) cpwait0(); else cpwait1();
        __syncthreads();
        if (c + 2 < C) fill(c + 2, (c + 2) % 3);
        int buf = c % 3;
        uint32_t ab = a_frag + buf * ABUF;
        uint32_t bb = b_frag + buf * BBUF;
        #pragma unroll
        for (int ks = 0; ks < 4; ks++) {
            uint32_t a0[4], a1[4], b[4][4];
            ldsm4(a0, ab + ks * 32);
            ldsm4(a1, ab + ks * 32 + 16 * A_STRIDE * 2);
            #pragma unroll
            for (int jp = 0; jp < 4; jp++)
                ldsm4t(b[jp], bb + jp * 32 + ks * (16 * B_STRIDE * 2));
            #pragma unroll
            for (int jp = 0; jp < 4; jp++) {
                mma16816(acc[0][jp * 2 + 0], a0, b[jp][0], b[jp][1]);
                mma16816(acc[1][jp * 2 + 0], a1, b[jp][0], b[jp][1]);
                mma16816(acc[0][jp * 2 + 1], a0, b[jp][2], b[jp][3]);
                mma16816(acc[1][jp * 2 + 1], a1, b[jp][2], b[jp][3]);
            }
        }
    }

    __half* yb = g_y + (size_t)job * CAP * KDIM;
    for (int am = 0; am < 2; am++) {
        for (int h = 0; h < 2; h++) {
            int r   = wm + am * 16 + (lane >> 2) + h * 8;
            int pos = base + r;
            if (pos >= cnt) continue;
            __half* orow = yb + (size_t)pos * KDIM;
            for (int j = 0; j < 8; j++) {
                int col = n0 + wn + (j >> 1) * 16 + (j & 1) * 8 + (lane & 3) * 2;
                *(__half2*)(orow + col) =
                    __floats2half2_rn(acc[am][j][h * 2 + 0], acc[am][j][h * 2 + 1]);
            }
        }
    }
}

// ---------------- kernel: combine routed + shared -> out; reset counters ----
__global__ __launch_bounds__(256) void k_combine(float* __restrict__ out,
                                                 const float* __restrict__ probs) {
    const int t = blockIdx.x;
    const uint4* y0 = (const uint4*)(g_y + (size_t)g_slot[t * TOPK + 0] * KDIM);
    const uint4* y1 = (const uint4*)(g_y + (size_t)g_slot[t * TOPK + 1] * KDIM);
    const uint4* ys = (const uint4*)(g_y + (size_t)(NEXP * CAP + t) * KDIM);
    const float p0 = probs[t * TOPK + 0];
    const float p1 = probs[t * TOPK + 1];
    float4* o = (float4*)(out + (size_t)t * KDIM);
    const int i = threadIdx.x;
    uint4 a = y0[i], b = y1[i], s = ys[i];
    const uint32_t* ap = (const uint32_t*)&a;
    const uint32_t* bp = (const uint32_t*)&b;
    const uint32_t* sp = (const uint32_t*)&s;
    float4 r0, r1;
    for (int j = 0; j < 4; j++) {
        float2 fa = __half22float2(*(const __half2*)&ap[j]);
        float2 fb = __half22float2(*(const __half2*)&bp[j]);
        float2 fs = __half22float2(*(const __half2*)&sp[j]);
        float* dst = (j < 2) ? ((float*)&r0 + j * 2) : ((float*)&r1 + (j - 2) * 2);
        dst[0] = p0 * fa.x + p1 * fb.x + fs.x;
        dst[1] = p0 * fa.y + p1 * fb.y + fs.y;
    }
    o[i * 2]     = r0;
    o[i * 2 + 1] = r1;
    if (blockIdx.x == 0 && threadIdx.x < NJOBS) g_cnt[threadIdx.x] = 0;
}

// ---------------- launcher ----------------
extern "C" void kernel_launch(void* const* d_in, const int* in_sizes, int n_in,
                              void* d_out, int out_size) {
    const float* x     = (const float*)d_in[0];
    const int*   gup   = (const int*)  d_in[1];
    const float* gus   = (const float*)d_in[2];
    const int*   dwp   = (const int*)  d_in[3];
    const float* dws   = (const float*)d_in[4];
    const int*   sgup  = (const int*)  d_in[5];
    const float* sgus  = (const float*)d_in[6];
    const int*   sdp   = (const int*)  d_in[7];
    const float* sds   = (const float*)d_in[8];
    const int*   ids   = (const int*)  d_in[9];
    const float* probs = (const float*)d_in[10];
    float* out = (float*)d_out;

    cudaFuncSetAttribute(k_gemm1, cudaFuncAttributeMaxDynamicSharedMemorySize, DSMEM);
    cudaFuncSetAttribute(k_gemm2, cudaFuncAttributeMaxDynamicSharedMemorySize, DSMEM);

    __half* wgu;
    __half* wd;
    cudaGetSymbolAddress((void**)&wgu, g_wgu);
    cudaGetSymbolAddress((void**)&wd,  g_wd);

    // Launch order keeps k_gemm1 at profile slot #4.
    k_x2h  <<<(T_TOK * KDIM) / 256, 256>>>(x);                                  // 1
    k_route<<<T_TOK / 256, 256>>>(ids);                                         // 2
    k_dq<<<dim3(256, NJOBS, 2), 256>>>(gup, gus, sgup, sgus,                    // 3
                                       dwp, dws, sdp, sds, wgu, wd);
    k_gemm1<<<dim3(CAP / 128, IDIM / 64, NJOBS), 256, DSMEM>>>();               // 4
    k_gemm2<<<dim3(CAP / 128, KDIM / 128, NJOBS), 256, DSMEM>>>();              // 5
    k_combine<<<T_TOK, 256>>>(out, probs);                                      // 6
}